// round 1
// baseline (speedup 1.0000x reference)
#include <cuda_runtime.h>
#include <cuda_bf16.h>

#define SEQ   512
#define BATCH 256
#define HID   128
#define MROWS (SEQ * BATCH)        /* 131072 */
#define ALPHA 0.1f

typedef unsigned long long u64;

/* ------------------------------------------------------------------ */
/* packed f32x2 helpers (sm_10x: fma.rn.f32x2 = 2 MACs per inst)      */
/* ------------------------------------------------------------------ */
__device__ __forceinline__ u64 pack2(float lo, float hi) {
    u64 r;
    asm("mov.b64 %0, {%1, %2};" : "=l"(r) : "f"(lo), "f"(hi));
    return r;
}
__device__ __forceinline__ float2 unpack2(u64 v) {
    float2 f;
    asm("mov.b64 {%0, %1}, %2;" : "=f"(f.x), "=f"(f.y) : "l"(v));
    return f;
}
__device__ __forceinline__ void fma2(u64 &acc, u64 a, u64 b) {
    asm("fma.rn.f32x2 %0, %1, %2, %0;" : "+l"(acc) : "l"(a), "l"(b));
}

/* scratch (device globals: allocation-free rule) */
__device__ float g_xp[MROWS * HID];   /* 67 MB  : x @ W_ih^T + biases  */
__device__ float g_hs[MROWS * HID];   /* 67 MB  : scan outputs         */
__device__ float g_y1[MROWS * 64];    /* 33.5MB : MLP layer-1 output   */

/* ------------------------------------------------------------------ */
/* Generic GEMM: C[M][BN] = A[M][K] * Bt[BN][K]^T + bias (+opt leaky) */
/* BM=64, BK=16, 256 threads, thread tile 4 x (BN/16), f32x2 inner    */
/* ------------------------------------------------------------------ */
template<int BN, bool LEAKY, bool TWO_BIAS>
__global__ __launch_bounds__(256)
void gemm_kernel(const float* __restrict__ A, const float* __restrict__ Bt,
                 const float* __restrict__ bias1, const float* __restrict__ bias2,
                 float* __restrict__ C, int M, int K)
{
    constexpr int BM = 64, BK = 16, TM = 4;
    constexpr int TN = BN / 16;
    constexpr int AST = 68;                 /* padded A-tile stride      */

    __shared__ __align__(16) float As[BK * AST];
    __shared__ __align__(16) float Bs[BK * BN];

    const int tid = threadIdx.x;
    const int tx  = tid & 15;
    const int ty  = tid >> 4;
    const int blockM = blockIdx.x * BM;

    u64 acc[TM][TN / 2];
#pragma unroll
    for (int i = 0; i < TM; i++)
#pragma unroll
        for (int j = 0; j < TN / 2; j++) acc[i][j] = 0ull;

    /* A-tile load mapping: one float4 per thread per tile */
    const int lm  = tid >> 2;               /* row within tile 0..63     */
    const int lk4 = (tid & 3) * 4;          /* k offset 0,4,8,12         */
    const float* Arow = A + (long)(blockM + lm) * K;

    /* B-tile load mapping */
    constexpr int BCNT = (BK * BN) / 256;
    const int bn  = tid % BN;
    const int bkb = (tid / BN) * BCNT;

    const int nTiles = (K + BK - 1) / BK;
    for (int kt = 0; kt < nTiles; ++kt) {
        const int k0 = kt * BK;

        /* load A tile (K is a multiple of 4 for both uses -> whole-vec pred) */
        float4 av = make_float4(0.f, 0.f, 0.f, 0.f);
        if (k0 + lk4 < K) av = *(const float4*)(Arow + k0 + lk4);
        As[(lk4 + 0) * AST + lm] = av.x;
        As[(lk4 + 1) * AST + lm] = av.y;
        As[(lk4 + 2) * AST + lm] = av.z;
        As[(lk4 + 3) * AST + lm] = av.w;

        /* load B tile (W is tiny -> L2 resident, coalescing noncritical) */
#pragma unroll
        for (int i = 0; i < BCNT; i++) {
            const int kk = bkb + i;
            Bs[kk * BN + bn] = (k0 + kk < K) ? Bt[bn * K + k0 + kk] : 0.f;
        }
        __syncthreads();

#pragma unroll
        for (int kk = 0; kk < BK; ++kk) {
            const float4 a4 = *(const float4*)&As[kk * AST + ty * TM];
            float ar[TM] = {a4.x, a4.y, a4.z, a4.w};

            u64 bp[TN / 2];
            const float4* Bv = (const float4*)&Bs[kk * BN + tx * TN];
#pragma unroll
            for (int j4 = 0; j4 < TN / 4; ++j4) {
                const float4 b4 = Bv[j4];
                bp[j4 * 2 + 0] = pack2(b4.x, b4.y);
                bp[j4 * 2 + 1] = pack2(b4.z, b4.w);
            }
#pragma unroll
            for (int i = 0; i < TM; i++) {
                const u64 ai = pack2(ar[i], ar[i]);
#pragma unroll
                for (int j = 0; j < TN / 2; j++) fma2(acc[i][j], ai, bp[j]);
            }
        }
        __syncthreads();
    }

    /* epilogue: bias (+bias2), optional leaky relu, store */
#pragma unroll
    for (int i = 0; i < TM; i++) {
        const int m = blockM + ty * TM + i;
        float* Crow = C + (long)m * BN;
#pragma unroll
        for (int j = 0; j < TN / 2; j++) {
            const float2 v = unpack2(acc[i][j]);
            const int n = tx * TN + 2 * j;
            float v0 = v.x + bias1[n]     + (TWO_BIAS ? bias2[n]     : 0.f);
            float v1 = v.y + bias1[n + 1] + (TWO_BIAS ? bias2[n + 1] : 0.f);
            if (LEAKY) {
                v0 = v0 > 0.f ? v0 : ALPHA * v0;
                v1 = v1 > 0.f ? v1 : ALPHA * v1;
            }
            Crow[n]     = v0;
            Crow[n + 1] = v1;
        }
    }
}

/* ------------------------------------------------------------------ */
/* Recurrence: h_t = tanh(xp_t + W_hh h_{t-1}); 128 CTAs x 2 batch    */
/* 512 thr: j = tid>>2 (hidden unit), seg = tid&3 (32-wide k slice).  */
/* W_hh row slice lives in registers; h in smem (seg-padded, ping-    */
/* pong); shfl.bfly reduction; one barrier per step.                  */
/* ------------------------------------------------------------------ */
__global__ __launch_bounds__(512)
void scan_kernel(const float* __restrict__ xp, const float* __restrict__ Whh,
                 float* __restrict__ hs)
{
    const int tid = threadIdx.x;
    const int j   = tid >> 2;        /* 0..127 */
    const int seg = tid & 3;         /* 0..3   */
    const int b0  = blockIdx.x * 2;

    __shared__ __align__(16) float hbuf[2][2][144];   /* [pp][b][seg*36+m] */

    /* weights: W_hh[j][seg*32 .. seg*32+31] as 16 packed pairs */
    u64 w[16];
    const u64* wp = (const u64*)(Whh + j * HID + seg * 32);
#pragma unroll
    for (int i = 0; i < 16; i++) w[i] = wp[i];

    /* h0 = 0 */
    for (int i = tid; i < 2 * 144; i += 512) ((float*)hbuf[0])[i] = 0.f;

    const bool writer = (seg < 2);
    const int  wb     = seg;         /* batch lane for writers */
    float xcur = 0.f;
    if (writer) xcur = xp[((long)0 * BATCH + b0 + wb) * HID + j];
    __syncthreads();

    int pp = 0;
    for (int t = 0; t < SEQ; ++t) {
        /* prefetch next x */
        float xnext = 0.f;
        if (writer && t + 1 < SEQ)
            xnext = xp[((long)(t + 1) * BATCH + b0 + wb) * HID + j];

        u64 acc0 = 0ull, acc1 = 0ull;
        const ulonglong2* h0p = (const ulonglong2*)&hbuf[pp][0][seg * 36];
        const ulonglong2* h1p = (const ulonglong2*)&hbuf[pp][1][seg * 36];
#pragma unroll
        for (int i = 0; i < 8; i++) {
            const ulonglong2 h0v = h0p[i];
            fma2(acc0, w[2 * i + 0], h0v.x);
            fma2(acc0, w[2 * i + 1], h0v.y);
            const ulonglong2 h1v = h1p[i];
            fma2(acc1, w[2 * i + 0], h1v.x);
            fma2(acc1, w[2 * i + 1], h1v.y);
        }
        const float2 a0 = unpack2(acc0);
        const float2 a1 = unpack2(acc1);
        float s0 = a0.x + a0.y;
        float s1 = a1.x + a1.y;
        s0 += __shfl_xor_sync(0xffffffffu, s0, 1);
        s0 += __shfl_xor_sync(0xffffffffu, s0, 2);
        s1 += __shfl_xor_sync(0xffffffffu, s1, 1);
        s1 += __shfl_xor_sync(0xffffffffu, s1, 2);

        if (writer) {
            const float v = xcur + (wb == 0 ? s0 : s1);
            /* tanh(v) = 1 - 2/(exp(2v)+1), MUFU-accurate (~2^-22) */
            const float e = __expf(v + v);
            const float h = 1.f - __fdividef(2.f, e + 1.f);
            hbuf[pp ^ 1][wb][j + (j >> 5) * 4] = h;
            hs[((long)t * BATCH + b0 + wb) * HID + j] = h;
        }
        xcur = xnext;
        pp ^= 1;
        __syncthreads();
    }
}

/* ------------------------------------------------------------------ */
/* MLP layers 2..5 fused, one thread per row; weights in smem         */
/* (pure-broadcast reads, conflict-free).                             */
/* ------------------------------------------------------------------ */
__global__ __launch_bounds__(256)
void mlp_tail_kernel(const float* __restrict__ Y1,
                     const float* __restrict__ W2, const float* __restrict__ b2,
                     const float* __restrict__ W3, const float* __restrict__ b3,
                     const float* __restrict__ W4, const float* __restrict__ b4,
                     const float* __restrict__ W5, const float* __restrict__ b5,
                     float* __restrict__ out, int M)
{
    __shared__ __align__(8) float sW2[32 * 64];
    __shared__ __align__(8) float sW3[16 * 32];
    __shared__ __align__(8) float sW4[8 * 16];
    __shared__ __align__(8) float sW5[8];
    __shared__ float sb2[32], sb3[16], sb4[8], sb5;

    const int tid = threadIdx.x;
    for (int i = tid; i < 2048; i += 256) sW2[i] = W2[i];
    for (int i = tid; i < 512;  i += 256) sW3[i] = W3[i];
    if (tid < 128) sW4[tid] = W4[tid];
    if (tid < 32)  sb2[tid] = b2[tid];
    if (tid < 16)  sb3[tid] = b3[tid];
    if (tid < 8) { sb4[tid] = b4[tid]; sW5[tid] = W5[tid]; }
    if (tid == 0)  sb5 = b5[0];
    __syncthreads();

    const int row = blockIdx.x * 256 + tid;
    if (row >= M) return;

    /* load y1 row -> packed pairs */
    const float* a = Y1 + (long)row * 64;
    u64 ap[32];
#pragma unroll
    for (int i = 0; i < 16; i++) {
        const float4 v = *(const float4*)(a + i * 4);
        ap[2 * i + 0] = pack2(v.x, v.y);
        ap[2 * i + 1] = pack2(v.z, v.w);
    }

    /* layer 2: 64 -> 32 */
    float y2[32];
    const u64* w2p = (const u64*)sW2;
#pragma unroll
    for (int o = 0; o < 32; o++) {
        u64 acc = 0ull;
#pragma unroll
        for (int k = 0; k < 32; k++) fma2(acc, ap[k], w2p[o * 32 + k]);
        const float2 f = unpack2(acc);
        const float v = f.x + f.y + sb2[o];
        y2[o] = v > 0.f ? v : ALPHA * v;
    }

    /* layer 3: 32 -> 16 */
    u64 a2[16];
#pragma unroll
    for (int i = 0; i < 16; i++) a2[i] = pack2(y2[2 * i], y2[2 * i + 1]);
    float y3[16];
    const u64* w3p = (const u64*)sW3;
#pragma unroll
    for (int o = 0; o < 16; o++) {
        u64 acc = 0ull;
#pragma unroll
        for (int k = 0; k < 16; k++) fma2(acc, a2[k], w3p[o * 16 + k]);
        const float2 f = unpack2(acc);
        const float v = f.x + f.y + sb3[o];
        y3[o] = v > 0.f ? v : ALPHA * v;
    }

    /* layer 4: 16 -> 8 */
    u64 a3[8];
#pragma unroll
    for (int i = 0; i < 8; i++) a3[i] = pack2(y3[2 * i], y3[2 * i + 1]);
    float y4[8];
    const u64* w4p = (const u64*)sW4;
#pragma unroll
    for (int o = 0; o < 8; o++) {
        u64 acc = 0ull;
#pragma unroll
        for (int k = 0; k < 8; k++) fma2(acc, a3[k], w4p[o * 8 + k]);
        const float2 f = unpack2(acc);
        const float v = f.x + f.y + sb4[o];
        y4[o] = v > 0.f ? v : ALPHA * v;
    }

    /* layer 5: 8 -> 1 */
    u64 a4[4];
#pragma unroll
    for (int i = 0; i < 4; i++) a4[i] = pack2(y4[2 * i], y4[2 * i + 1]);
    const u64* w5p = (const u64*)sW5;
    u64 acc = 0ull;
#pragma unroll
    for (int k = 0; k < 4; k++) fma2(acc, a4[k], w5p[k]);
    const float2 f = unpack2(acc);
    float v = f.x + f.y + sb5;
    v = v > 0.f ? v : ALPHA * v;
    out[row] = v;
}

/* ------------------------------------------------------------------ */
extern "C" void kernel_launch(void* const* d_in, const int* in_sizes, int n_in,
                              void* d_out, int out_size)
{
    const float* x    = (const float*)d_in[0];
    const float* W_ih = (const float*)d_in[1];
    const float* W_hh = (const float*)d_in[2];
    const float* b_ih = (const float*)d_in[3];
    const float* b_hh = (const float*)d_in[4];
    const float* W1   = (const float*)d_in[5];
    const float* b1   = (const float*)d_in[6];
    const float* W2   = (const float*)d_in[7];
    const float* b2   = (const float*)d_in[8];
    const float* W3   = (const float*)d_in[9];
    const float* b3   = (const float*)d_in[10];
    const float* W4   = (const float*)d_in[11];
    const float* b4   = (const float*)d_in[12];
    const float* W5   = (const float*)d_in[13];
    const float* b5   = (const float*)d_in[14];
    float* out = (float*)d_out;

    float *xp, *hs, *y1;
    cudaGetSymbolAddress((void**)&xp, g_xp);
    cudaGetSymbolAddress((void**)&hs, g_hs);
    cudaGetSymbolAddress((void**)&y1, g_y1);

    /* 1) input projection: xp = x @ W_ih^T + b_ih + b_hh */
    gemm_kernel<128, false, true><<<MROWS / 64, 256>>>(x, W_ih, b_ih, b_hh, xp, MROWS, 300);

    /* 2) recurrence */
    scan_kernel<<<BATCH / 2, 512>>>(xp, W_hh, hs);

    /* 3) MLP layer 1 (128->64) as GEMM with fused leaky relu */
    gemm_kernel<64, true, false><<<MROWS / 64, 256>>>(hs, W1, b1, nullptr, y1, MROWS, HID);

    /* 4) MLP layers 2..5 fused */
    mlp_tail_kernel<<<MROWS / 256, 256>>>(y1, W2, b2, W3, b3, W4, b4, W5, b5, out, MROWS);
}

// round 2
// speedup vs baseline: 1.3450x; 1.3450x over previous
#include <cuda_runtime.h>
#include <cuda_bf16.h>

#define SEQ   512
#define BATCH 256
#define HID   128
#define MROWS (SEQ * BATCH)        /* 131072 */
#define KIN   300
#define KINP  304                  /* padded to BK multiple */
#define ALPHA 0.1f

typedef unsigned long long u64;

/* ------------------------------------------------------------------ */
/* packed f32x2 helpers (sm_10x: fma.rn.f32x2 = 2 MACs per inst)      */
/* ------------------------------------------------------------------ */
__device__ __forceinline__ u64 pack2(float lo, float hi) {
    u64 r;
    asm("mov.b64 %0, {%1, %2};" : "=l"(r) : "f"(lo), "f"(hi));
    return r;
}
__device__ __forceinline__ float2 unpack2(u64 v) {
    float2 f;
    asm("mov.b64 {%0, %1}, %2;" : "=f"(f.x), "=f"(f.y) : "l"(v));
    return f;
}
__device__ __forceinline__ void fma2(u64 &acc, u64 a, u64 b) {
    asm("fma.rn.f32x2 %0, %1, %2, %0;" : "+l"(acc) : "l"(a), "l"(b));
}

/* scratch (device globals: allocation-free rule) */
__device__ float g_xp[MROWS * HID];        /* 67 MB : proj output       */
__device__ float g_hs[MROWS * HID];        /* 67 MB : scan outputs      */
__device__ float g_WTih[KINP * HID];       /* W_ih^T, k-major, padded   */
__device__ float g_WT1[HID * 64];          /* W1^T, k-major             */
__device__ float g_bias[HID];              /* b_ih + b_hh               */

/* ------------------------------------------------------------------ */
/* prep: transpose weights to k-major, combine biases                 */
/* ------------------------------------------------------------------ */
__global__ void prep_kernel(const float* __restrict__ W_ih,
                            const float* __restrict__ W1,
                            const float* __restrict__ b_ih,
                            const float* __restrict__ b_hh)
{
    const int i = blockIdx.x * 256 + threadIdx.x;
    if (i < KINP * HID) {
        const int k = i >> 7, n = i & 127;
        g_WTih[i] = (k < KIN) ? W_ih[n * KIN + k] : 0.f;
    }
    if (i < HID * 64) {
        const int k = i >> 6, n = i & 63;
        g_WT1[i] = W1[n * HID + k];
    }
    if (i < HID) g_bias[i] = b_ih[i] + b_hh[i];
}

/* ------------------------------------------------------------------ */
/* Input projection GEMM: xp[M][128] = x[M][300] * WTih[304][128]     */
/* BM=128, BN=128, BK=16, 256 thr, thread tile 8x8, f32x2 inner      */
/* ------------------------------------------------------------------ */
__global__ __launch_bounds__(256)
void proj_kernel(const float* __restrict__ A, const float* __restrict__ WT,
                 const float* __restrict__ bias, float* __restrict__ C)
{
    constexpr int BN = 128, BK = 16, AST = 132;
    __shared__ __align__(16) float As[BK * AST];
    __shared__ __align__(16) float Bs[BK * BN];

    const int tid = threadIdx.x;
    const int tx  = tid & 15;           /* n group */
    const int ty  = tid >> 4;           /* m group */
    const int blockM = blockIdx.x * 128;

    u64 acc[8][4];
#pragma unroll
    for (int i = 0; i < 8; i++)
#pragma unroll
        for (int j = 0; j < 4; j++) acc[i][j] = 0ull;

    const int lr  = tid >> 2;           /* A-load row 0..63 (+64)    */
    const int lk4 = (tid & 3) * 4;      /* A-load k offset           */

    for (int kt = 0; kt < KINP / BK; ++kt) {
        const int k0 = kt * BK;

        /* A tile: 2 float4 per thread, guarded on K=300 */
#pragma unroll
        for (int h = 0; h < 2; h++) {
            const int row = lr + h * 64;
            float4 av = make_float4(0.f, 0.f, 0.f, 0.f);
            if (k0 + lk4 < KIN)
                av = *(const float4*)(A + (long)(blockM + row) * KIN + k0 + lk4);
            As[(lk4 + 0) * AST + row] = av.x;
            As[(lk4 + 1) * AST + row] = av.y;
            As[(lk4 + 2) * AST + row] = av.z;
            As[(lk4 + 3) * AST + row] = av.w;
        }
        /* B tile: fully coalesced from k-major WT */
#pragma unroll
        for (int h = 0; h < 2; h++)
            *(float4*)&Bs[tid * 4 + h * 1024] =
                *(const float4*)(WT + k0 * BN + tid * 4 + h * 1024);
        __syncthreads();

#pragma unroll
        for (int kk = 0; kk < BK; ++kk) {
            const float4 a0 = *(const float4*)&As[kk * AST + ty * 8];
            const float4 a1 = *(const float4*)&As[kk * AST + ty * 8 + 4];
            const float4 b0 = *(const float4*)&Bs[kk * BN + tx * 8];
            const float4 b1 = *(const float4*)&Bs[kk * BN + tx * 8 + 4];
            u64 bp[4] = { pack2(b0.x, b0.y), pack2(b0.z, b0.w),
                          pack2(b1.x, b1.y), pack2(b1.z, b1.w) };
            const float ar[8] = {a0.x, a0.y, a0.z, a0.w, a1.x, a1.y, a1.z, a1.w};
#pragma unroll
            for (int i = 0; i < 8; i++) {
                const u64 ai = pack2(ar[i], ar[i]);
#pragma unroll
                for (int j = 0; j < 4; j++) fma2(acc[i][j], ai, bp[j]);
            }
        }
        __syncthreads();
    }

#pragma unroll
    for (int i = 0; i < 8; i++) {
        float* Crow = C + (long)(blockM + ty * 8 + i) * BN;
#pragma unroll
        for (int j = 0; j < 4; j++) {
            const float2 v = unpack2(acc[i][j]);
            const int n = tx * 8 + 2 * j;
            float2 o = make_float2(v.x + bias[n], v.y + bias[n + 1]);
            *(float2*)(Crow + n) = o;
        }
    }
}

/* ------------------------------------------------------------------ */
/* Recurrence: h_t = tanh(xp_t + W_hh h_{t-1}); 128 CTAs x 2 batch    */
/* ------------------------------------------------------------------ */
__global__ __launch_bounds__(512)
void scan_kernel(const float* __restrict__ xp, const float* __restrict__ Whh,
                 float* __restrict__ hs)
{
    const int tid = threadIdx.x;
    const int j   = tid >> 2;
    const int seg = tid & 3;
    const int b0  = blockIdx.x * 2;

    __shared__ __align__(16) float hbuf[2][2][144];

    u64 w[16];
    const u64* wp = (const u64*)(Whh + j * HID + seg * 32);
#pragma unroll
    for (int i = 0; i < 16; i++) w[i] = wp[i];

    for (int i = tid; i < 2 * 144; i += 512) ((float*)hbuf[0])[i] = 0.f;

    const bool writer = (seg < 2);
    const int  wb     = seg;
    float xcur = 0.f;
    if (writer) xcur = xp[((long)0 * BATCH + b0 + wb) * HID + j];
    __syncthreads();

    int pp = 0;
    for (int t = 0; t < SEQ; ++t) {
        float xnext = 0.f;
        if (writer && t + 1 < SEQ)
            xnext = xp[((long)(t + 1) * BATCH + b0 + wb) * HID + j];

        u64 acc0 = 0ull, acc1 = 0ull;
        const ulonglong2* h0p = (const ulonglong2*)&hbuf[pp][0][seg * 36];
        const ulonglong2* h1p = (const ulonglong2*)&hbuf[pp][1][seg * 36];
#pragma unroll
        for (int i = 0; i < 8; i++) {
            const ulonglong2 h0v = h0p[i];
            fma2(acc0, w[2 * i + 0], h0v.x);
            fma2(acc0, w[2 * i + 1], h0v.y);
            const ulonglong2 h1v = h1p[i];
            fma2(acc1, w[2 * i + 0], h1v.x);
            fma2(acc1, w[2 * i + 1], h1v.y);
        }
        const float2 a0 = unpack2(acc0);
        const float2 a1 = unpack2(acc1);
        float s0 = a0.x + a0.y;
        float s1 = a1.x + a1.y;
        s0 += __shfl_xor_sync(0xffffffffu, s0, 1);
        s0 += __shfl_xor_sync(0xffffffffu, s0, 2);
        s1 += __shfl_xor_sync(0xffffffffu, s1, 1);
        s1 += __shfl_xor_sync(0xffffffffu, s1, 2);

        if (writer) {
            const float v = xcur + (wb == 0 ? s0 : s1);
            const float e = __expf(v + v);
            const float h = 1.f - __fdividef(2.f, e + 1.f);
            hbuf[pp ^ 1][wb][j + (j >> 5) * 4] = h;
            hs[((long)t * BATCH + b0 + wb) * HID + j] = h;
        }
        xcur = xnext;
        pp ^= 1;
        __syncthreads();
    }
}

/* ------------------------------------------------------------------ */
/* Fused MLP: L1 GEMM (128->64) into smem, then L2..L5 from smem.     */
/* BM=128, BN=64, BK=16, 256 thr; y1 never touches DRAM.              */
/* ------------------------------------------------------------------ */
__global__ __launch_bounds__(256)
void mlp_kernel(const float* __restrict__ A, const float* __restrict__ WT1,
                const float* __restrict__ b1,
                const float* __restrict__ W2, const float* __restrict__ b2,
                const float* __restrict__ W3, const float* __restrict__ b3,
                const float* __restrict__ W4, const float* __restrict__ b4,
                const float* __restrict__ W5, const float* __restrict__ b5,
                float* __restrict__ out)
{
    constexpr int BN = 64, BK = 16, AST = 132, YST = 66;
    __shared__ __align__(16) float As[BK * AST];   /* reused as sW2 (2048) */
    __shared__ __align__(16) float Bs[BK * BN];    /* reused as tail wts   */
    __shared__ __align__(16) float y1s[128 * YST];

    const int tid = threadIdx.x;
    const int tx  = tid & 15;
    const int ty  = tid >> 4;
    const int blockM = blockIdx.x * 128;

    u64 acc[8][2];
#pragma unroll
    for (int i = 0; i < 8; i++) { acc[i][0] = 0ull; acc[i][1] = 0ull; }

    const int lr  = tid >> 2;
    const int lk4 = (tid & 3) * 4;

    for (int kt = 0; kt < HID / BK; ++kt) {
        const int k0 = kt * BK;
#pragma unroll
        for (int h = 0; h < 2; h++) {
            const int row = lr + h * 64;
            const float4 av = *(const float4*)(A + (long)(blockM + row) * HID + k0 + lk4);
            As[(lk4 + 0) * AST + row] = av.x;
            As[(lk4 + 1) * AST + row] = av.y;
            As[(lk4 + 2) * AST + row] = av.z;
            As[(lk4 + 3) * AST + row] = av.w;
        }
        *(float4*)&Bs[tid * 4] = *(const float4*)(WT1 + k0 * BN + tid * 4);
        __syncthreads();

#pragma unroll
        for (int kk = 0; kk < BK; ++kk) {
            const float4 a0 = *(const float4*)&As[kk * AST + ty * 8];
            const float4 a1 = *(const float4*)&As[kk * AST + ty * 8 + 4];
            const float4 b0 = *(const float4*)&Bs[kk * BN + tx * 4];
            const u64 bp[2] = { pack2(b0.x, b0.y), pack2(b0.z, b0.w) };
            const float ar[8] = {a0.x, a0.y, a0.z, a0.w, a1.x, a1.y, a1.z, a1.w};
#pragma unroll
            for (int i = 0; i < 8; i++) {
                const u64 ai = pack2(ar[i], ar[i]);
                fma2(acc[i][0], ai, bp[0]);
                fma2(acc[i][1], ai, bp[1]);
            }
        }
        __syncthreads();
    }

    /* epilogue into smem + load tail weights into reused As/Bs */
#pragma unroll
    for (int i = 0; i < 8; i++) {
        const int m = ty * 8 + i;
#pragma unroll
        for (int j = 0; j < 2; j++) {
            const float2 v = unpack2(acc[i][j]);
            const int n = tx * 4 + 2 * j;
            float v0 = v.x + b1[n];
            float v1 = v.y + b1[n + 1];
            v0 = v0 > 0.f ? v0 : ALPHA * v0;
            v1 = v1 > 0.f ? v1 : ALPHA * v1;
            *(float2*)&y1s[m * YST + n] = make_float2(v0, v1);
        }
    }

    float* const sW2 = As;                 /* 2048 floats              */
    float* const sW3 = Bs;                 /* 512                      */
    float* const sW4 = Bs + 512;           /* 128                      */
    float* const sW5 = Bs + 640;           /* 8                        */
    float* const sb2 = Bs + 648;           /* 32                       */
    float* const sb3 = Bs + 680;           /* 16                       */
    float* const sb4 = Bs + 696;           /* 8                        */
    float* const sb5 = Bs + 704;           /* 1                        */

    for (int i = tid; i < 2048; i += 256) sW2[i] = W2[i];
    for (int i = tid; i < 512;  i += 256) sW3[i] = W3[i];
    if (tid < 128) sW4[tid] = W4[tid];
    if (tid < 32)  sb2[tid] = b2[tid];
    if (tid < 16)  sb3[tid] = b3[tid];
    if (tid < 8) { sb4[tid] = b4[tid]; sW5[tid] = W5[tid]; }
    if (tid == 0)  sb5[0] = b5[0];
    __syncthreads();

    if (tid >= 128) return;
    const int row = tid;

    /* y1 row -> packed pairs (stride-66 float2: 2-way max conflict)  */
    u64 ap[32];
    const float2* yr = (const float2*)&y1s[row * YST];
#pragma unroll
    for (int i = 0; i < 32; i++) {
        const float2 v = yr[i];
        ap[i] = pack2(v.x, v.y);
    }

    /* layer 2: 64 -> 32 */
    float y2[32];
    const u64* w2p = (const u64*)sW2;
#pragma unroll
    for (int o = 0; o < 32; o++) {
        u64 a = 0ull;
#pragma unroll
        for (int k = 0; k < 32; k++) fma2(a, ap[k], w2p[o * 32 + k]);
        const float2 f = unpack2(a);
        const float v = f.x + f.y + sb2[o];
        y2[o] = v > 0.f ? v : ALPHA * v;
    }

    /* layer 3: 32 -> 16 */
    u64 a2[16];
#pragma unroll
    for (int i = 0; i < 16; i++) a2[i] = pack2(y2[2 * i], y2[2 * i + 1]);
    float y3[16];
    const u64* w3p = (const u64*)sW3;
#pragma unroll
    for (int o = 0; o < 16; o++) {
        u64 a = 0ull;
#pragma unroll
        for (int k = 0; k < 16; k++) fma2(a, a2[k], w3p[o * 16 + k]);
        const float2 f = unpack2(a);
        const float v = f.x + f.y + sb3[o];
        y3[o] = v > 0.f ? v : ALPHA * v;
    }

    /* layer 4: 16 -> 8 */
    u64 a3[8];
#pragma unroll
    for (int i = 0; i < 8; i++) a3[i] = pack2(y3[2 * i], y3[2 * i + 1]);
    float y4[8];
    const u64* w4p = (const u64*)sW4;
#pragma unroll
    for (int o = 0; o < 8; o++) {
        u64 a = 0ull;
#pragma unroll
        for (int k = 0; k < 8; k++) fma2(a, a3[k], w4p[o * 8 + k]);
        const float2 f = unpack2(a);
        const float v = f.x + f.y + sb4[o];
        y4[o] = v > 0.f ? v : ALPHA * v;
    }

    /* layer 5: 8 -> 1 */
    u64 a4[4];
#pragma unroll
    for (int i = 0; i < 4; i++) a4[i] = pack2(y4[2 * i], y4[2 * i + 1]);
    const u64* w5p = (const u64*)sW5;
    u64 a = 0ull;
#pragma unroll
    for (int k = 0; k < 4; k++) fma2(a, a4[k], w5p[k]);
    const float2 f = unpack2(a);
    float v = f.x + f.y + sb5[0];
    v = v > 0.f ? v : ALPHA * v;
    out[blockM + row] = v;
}

/* ------------------------------------------------------------------ */
extern "C" void kernel_launch(void* const* d_in, const int* in_sizes, int n_in,
                              void* d_out, int out_size)
{
    const float* x    = (const float*)d_in[0];
    const float* W_ih = (const float*)d_in[1];
    const float* W_hh = (const float*)d_in[2];
    const float* b_ih = (const float*)d_in[3];
    const float* b_hh = (const float*)d_in[4];
    const float* W1   = (const float*)d_in[5];
    const float* b1   = (const float*)d_in[6];
    const float* W2   = (const float*)d_in[7];
    const float* b2   = (const float*)d_in[8];
    const float* W3   = (const float*)d_in[9];
    const float* b3   = (const float*)d_in[10];
    const float* W4   = (const float*)d_in[11];
    const float* b4   = (const float*)d_in[12];
    const float* W5   = (const float*)d_in[13];
    const float* b5   = (const float*)d_in[14];
    float* out = (float*)d_out;

    float *xp, *hs, *WTih, *WT1, *bias;
    cudaGetSymbolAddress((void**)&xp,   g_xp);
    cudaGetSymbolAddress((void**)&hs,   g_hs);
    cudaGetSymbolAddress((void**)&WTih, g_WTih);
    cudaGetSymbolAddress((void**)&WT1,  g_WT1);
    cudaGetSymbolAddress((void**)&bias, g_bias);

    prep_kernel<<<(KINP * HID + 255) / 256, 256>>>(W_ih, W1, b_ih, b_hh);
    proj_kernel<<<MROWS / 128, 256>>>(x, WTih, bias, xp);
    scan_kernel<<<BATCH / 2, 512>>>(xp, W_hh, hs);
    mlp_kernel<<<MROWS / 128, 256>>>(hs, WT1, b1, W2, b2, W3, b3, W4, b4, W5, b5, out);
}